// round 1
// baseline (speedup 1.0000x reference)
#include <cuda_runtime.h>
#include <cstdint>

#define BB 8
#define CC 64
#define OO 64
#define HH 96
#define WW 96
#define HW (HH*WW)          // 9216
#define K2 9
#define NOFF 18             // 2*K*K

// ---------------- scratch (static device allocations are allowed) ----------
__device__ float g_xt[BB * HW * CC];       // x transposed to NHWC  (~18.9 MB)
__device__ float g_offs[BB * HW * NOFF];   // offset field, pixel-major (~5.3 MB)
__device__ float g_wt[576 * OO];           // conv_w re-laid as [k*64+c][o] (147 KB)

// ---------------- kernel T1: NCHW -> NHWC transpose ------------------------
__global__ void transpose_x_kernel(const float* __restrict__ x, float* __restrict__ xt) {
    __shared__ float tile[32][33];
    int blk = blockIdx.x;            // 8 * 2 * 288 = 4608 blocks
    int pt  = blk % 288;             // pixel tile (32 pixels)
    int ct  = (blk / 288) & 1;       // channel tile (32 channels)
    int b   = blk / 576;
    int lx = threadIdx.x & 31, ly = threadIdx.x >> 5;   // ly in 0..7
    int p0 = pt * 32, c0 = ct * 32;
    const float* xb = x + (size_t)(b * CC + c0) * HW + p0;
#pragma unroll
    for (int i = 0; i < 4; i++) {
        int cc = ly + 8 * i;
        tile[cc][lx] = xb[(size_t)cc * HW + lx];
    }
    __syncthreads();
    float* xo = xt + (size_t)(b * HW + p0) * CC + c0;
#pragma unroll
    for (int i = 0; i < 4; i++) {
        int pp = ly + 8 * i;
        xo[(size_t)pp * CC + lx] = tile[lx][pp];
    }
}

// ---------------- kernel T2: conv_w (O,C,3,3) -> w_t[(k*64+c)*64+o] --------
__global__ void build_wt_kernel(const float* __restrict__ cw, float* __restrict__ wt) {
    int idx = blockIdx.x * 256 + threadIdx.x;   // 36864 elems
    if (idx < OO * CC * K2) {
        int o = idx / (CC * K2);
        int r = idx % (CC * K2);
        int c = r / K2;
        int k = r % K2;
        wt[(k * CC + c) * OO + o] = cw[idx];
    }
}

// ---------------- kernel 1: offset conv (18 out ch), 2 pixels / thread -----
__global__ void __launch_bounds__(256) offset_conv_kernel(
    const float* __restrict__ x, const float* __restrict__ ow,
    const float* __restrict__ ob, float* __restrict__ offs)
{
    __shared__ float ws[NOFF * CC * K2];    // 10368 floats = 41.5 KB
    __shared__ float bs[NOFF];
    int tid = threadIdx.x;
    for (int i = tid; i < NOFF * CC * K2; i += 256) ws[i] = ow[i];
    if (tid < NOFF) bs[tid] = ob[tid];
    __syncthreads();

    int flat = blockIdx.x * 256 + tid;     // 0 .. 36863  (first half of pixels)
    int b = flat / HW, p = flat % HW;
    int h = p / WW, w = p % WW;
    const float* x0 = x + (size_t)b * CC * HW;
    const float* x1 = x0 + (size_t)4 * CC * HW;   // pixel #2: same (p), batch b+4

    float acc0[NOFF], acc1[NOFF];
#pragma unroll
    for (int j = 0; j < NOFF; j++) { acc0[j] = 0.f; acc1[j] = 0.f; }

    int yy[3], xx[3]; bool vy[3], vx[3];
#pragma unroll
    for (int d = 0; d < 3; d++) {
        yy[d] = h + d - 1; vy[d] = (unsigned)yy[d] < (unsigned)HH;
        xx[d] = w + d - 1; vx[d] = (unsigned)xx[d] < (unsigned)WW;
    }

    for (int c = 0; c < CC; c++) {
        float xv0[9], xv1[9];
        const float* xc0 = x0 + (size_t)c * HW;
        const float* xc1 = x1 + (size_t)c * HW;
#pragma unroll
        for (int dy = 0; dy < 3; dy++)
#pragma unroll
            for (int dx = 0; dx < 3; dx++) {
                int i = dy * 3 + dx;
                bool v = vy[dy] && vx[dx];
                int off = yy[dy] * WW + xx[dx];
                xv0[i] = v ? xc0[off] : 0.f;
                xv1[i] = v ? xc1[off] : 0.f;
            }
#pragma unroll
        for (int j = 0; j < NOFF; j++) {
            const float* wj = ws + j * (CC * K2) + c * K2;
#pragma unroll
            for (int i = 0; i < 9; i++) {
                float wv = wj[i];
                acc0[j] += xv0[i] * wv;
                acc1[j] += xv1[i] * wv;
            }
        }
    }
    float* o0 = offs + (size_t)flat * NOFF;
    float* o1 = offs + (size_t)(flat + 36864) * NOFF;
#pragma unroll
    for (int j = 0; j < NOFF; j++) { o0[j] = acc0[j] + bs[j]; o1[j] = acc1[j] + bs[j]; }
}

// ---------------- kernel 2: fused bilinear sampling + 576-deep GEMM --------
// CTA: 256 threads, 32 pixels. smem: samp[32][584] + ws[64][64] + positions.
#define SAMP_STRIDE 584
#define SMEM_FUSED ((32*SAMP_STRIDE + 64*64 + 4*288) * 4)   // 95744 B

__global__ void __launch_bounds__(256) fused_deform_kernel(
    const float* __restrict__ xt, const float* __restrict__ offs,
    const float* __restrict__ wt, const float* __restrict__ cb,
    float* __restrict__ out)
{
    extern __shared__ float sm[];
    float* samp = sm;                          // 32 * 584
    float* ws   = sm + 32 * SAMP_STRIDE;       // 64 * 64
    int*   y0s  = (int*)(ws + 64 * 64);        // 288
    int*   x0s  = y0s + 288;
    float* wys  = (float*)(x0s + 288);
    float* wxs  = wys + 288;

    int tid = threadIdx.x;
    int b   = blockIdx.x / 288;
    int p0  = (blockIdx.x % 288) * 32;

    // ---- Phase A: bilinear positions for 32 pixels x 9 taps ----
    for (int t = tid; t < 288; t += 256) {
        int i = t / 9, k = t % 9;
        int p = p0 + i;
        int h = p / WW, w = p % WW;
        const float* op = offs + ((size_t)(b * HW + p)) * NOFF + 2 * k;
        float dy = op[0];
        float dx = op[1];
        float py = (float)(h - 1 + k / 3) + dy;
        float px = (float)(w - 1 + k % 3) + dx;
        float fy = floorf(py), fx = floorf(px);
        y0s[t] = (int)fy; x0s[t] = (int)fx;
        wys[t] = py - fy;  wxs[t] = px - fx;
    }
    __syncthreads();

    // ---- Phase B: sample 32*9*64 values into smem (coalesced from NHWC) ----
    int lane = tid & 31;
    int warp = tid >> 5;
    const float* xb = xt + (size_t)b * HW * CC;
    for (int pair = warp; pair < 288; pair += 8) {
        int i = pair / 9, k = pair % 9;
        int y0 = y0s[pair], x0 = x0s[pair];
        float wy = wys[pair], wx = wxs[pair];
        int c = lane * 2;
        bool vy0 = (unsigned)y0 < (unsigned)HH;
        bool vy1 = (unsigned)(y0 + 1) < (unsigned)HH;
        bool vx0 = (unsigned)x0 < (unsigned)WW;
        bool vx1 = (unsigned)(x0 + 1) < (unsigned)WW;
        const float* base = xb + ((ptrdiff_t)y0 * WW + x0) * CC + c;
        float2 z = make_float2(0.f, 0.f);
        float2 g00 = (vy0 && vx0) ? *(const float2*)(base)               : z;
        float2 g01 = (vy0 && vx1) ? *(const float2*)(base + CC)          : z;
        float2 g10 = (vy1 && vx0) ? *(const float2*)(base + WW*CC)       : z;
        float2 g11 = (vy1 && vx1) ? *(const float2*)(base + WW*CC + CC)  : z;
        float w00 = (1.f - wy) * (1.f - wx);
        float w01 = (1.f - wy) * wx;
        float w10 = wy * (1.f - wx);
        float w11 = wy * wx;
        float sx = g00.x * w00 + g01.x * w01 + g10.x * w10 + g11.x * w11;
        float sy = g00.y * w00 + g01.y * w01 + g10.y * w10 + g11.y * w11;
        *(float2*)(samp + i * SAMP_STRIDE + k * 64 + c) = make_float2(sx, sy);
    }

    // ---- Phase C: GEMM  out[32 pix][64 o] += samp[32][576] * wt[576][64] ----
    float acc[2][4];
#pragma unroll
    for (int a = 0; a < 2; a++)
#pragma unroll
        for (int q = 0; q < 4; q++) acc[a][q] = 0.f;

    int tx = tid & 15;          // 16 output groups of 4
    int ty = tid >> 4;          // 16 pixel groups of 2
    const float* sp0 = samp + (ty * 2) * SAMP_STRIDE;
    const float* sp1 = sp0 + SAMP_STRIDE;

    for (int ck = 0; ck < 9; ck++) {
        __syncthreads();
        // stage 64x64 weight chunk (chunk == kernel tap k)
        const float4* src = (const float4*)(wt + ck * 4096);
        float4* dst = (float4*)ws;
#pragma unroll
        for (int r = 0; r < 4; r++) dst[tid + 256 * r] = src[tid + 256 * r];
        __syncthreads();

        const float* s0p = sp0 + ck * 64;
        const float* s1p = sp1 + ck * 64;
#pragma unroll
        for (int kk = 0; kk < 64; kk += 2) {
            float2 s0 = *(const float2*)(s0p + kk);
            float2 s1 = *(const float2*)(s1p + kk);
            float4 w0 = *(const float4*)(ws + kk * 64 + tx * 4);
            float4 w1 = *(const float4*)(ws + kk * 64 + 64 + tx * 4);
            acc[0][0] += s0.x * w0.x; acc[0][1] += s0.x * w0.y;
            acc[0][2] += s0.x * w0.z; acc[0][3] += s0.x * w0.w;
            acc[1][0] += s1.x * w0.x; acc[1][1] += s1.x * w0.y;
            acc[1][2] += s1.x * w0.z; acc[1][3] += s1.x * w0.w;
            acc[0][0] += s0.y * w1.x; acc[0][1] += s0.y * w1.y;
            acc[0][2] += s0.y * w1.z; acc[0][3] += s0.y * w1.w;
            acc[1][0] += s1.y * w1.x; acc[1][1] += s1.y * w1.y;
            acc[1][2] += s1.y * w1.z; acc[1][3] += s1.y * w1.w;
        }
    }

    float4 b4 = *(const float4*)(cb + tx * 4);
    int p = p0 + ty * 2;
#pragma unroll
    for (int q = 0; q < 4; q++) {
        int o = tx * 4 + q;
        float bq = (q == 0) ? b4.x : (q == 1) ? b4.y : (q == 2) ? b4.z : b4.w;
        float2 v = make_float2(acc[0][q] + bq, acc[1][q] + bq);
        *(float2*)(out + ((size_t)(b * OO + o)) * HW + p) = v;
    }
}

// ---------------- launch ----------------------------------------------------
extern "C" void kernel_launch(void* const* d_in, const int* in_sizes, int n_in,
                              void* d_out, int out_size) {
    const float* x  = (const float*)d_in[0];   // (8,64,96,96)
    const float* ow = (const float*)d_in[1];   // (18,64,3,3)
    const float* ob = (const float*)d_in[2];   // (18,)
    const float* cw = (const float*)d_in[3];   // (64,64,3,3)
    const float* cb = (const float*)d_in[4];   // (64,)
    float* out = (float*)d_out;                // (8,64,96,96)

    float *xt, *offs, *wt;
    cudaGetSymbolAddress((void**)&xt,   g_xt);
    cudaGetSymbolAddress((void**)&offs, g_offs);
    cudaGetSymbolAddress((void**)&wt,   g_wt);

    cudaFuncSetAttribute(fused_deform_kernel,
                         cudaFuncAttributeMaxDynamicSharedMemorySize, SMEM_FUSED);

    transpose_x_kernel<<<4608, 256>>>(x, xt);
    build_wt_kernel<<<144, 256>>>(cw, wt);
    offset_conv_kernel<<<144, 256>>>(x, ow, ob, offs);
    fused_deform_kernel<<<2304, 256, SMEM_FUSED>>>(xt, offs, wt, cb, out);
}

// round 2
// speedup vs baseline: 1.3912x; 1.3912x over previous
#include <cuda_runtime.h>
#include <cstdint>

#define BB 8
#define CC 64
#define OO 64
#define HH 96
#define WW 96
#define HW (HH*WW)          // 9216
#define K2 9
#define NOFF 18             // 2*K*K

typedef unsigned long long ull;

#define PACKF2(d, lo, hi) asm("mov.b64 %0, {%1,%2};" : "=l"(d) : "f"(lo), "f"(hi))
#define UNPKF2(lo, hi, s) asm("mov.b64 {%0,%1}, %2;" : "=f"(lo), "=f"(hi) : "l"(s))
#define FMA2(d, a, b, c)  asm("fma.rn.f32x2 %0, %1, %2, %3;" : "=l"(d) : "l"(a), "l"(b), "l"(c))

// ---------------- scratch ----------------------------------------------------
__device__ float g_xt[BB * HW * CC];          // x in NHWC (~18.9 MB)
__device__ float g_offs[BB * HW * NOFF];      // offsets, pixel-major (~5.3 MB)
__device__ float g_wt[K2 * CC * OO];          // conv_w as [k][c][o] (147 KB)
__device__ float g_owt[CC * K2 * 20];         // offset_w as [c][tap][j pad 20]

// ---------------- kernel T1: NCHW -> NHWC transpose -------------------------
__global__ void transpose_x_kernel(const float* __restrict__ x, float* __restrict__ xt) {
    __shared__ float tile[32][33];
    int blk = blockIdx.x;            // 8 * 2 * 288
    int pt  = blk % 288;
    int ct  = (blk / 288) & 1;
    int b   = blk / 576;
    int lx = threadIdx.x & 31, ly = threadIdx.x >> 5;
    int p0 = pt * 32, c0 = ct * 32;
    const float* xb = x + (size_t)(b * CC + c0) * HW + p0;
#pragma unroll
    for (int i = 0; i < 4; i++) {
        int cc = ly + 8 * i;
        tile[cc][lx] = xb[(size_t)cc * HW + lx];
    }
    __syncthreads();
    float* xo = xt + (size_t)(b * HW + p0) * CC + c0;
#pragma unroll
    for (int i = 0; i < 4; i++) {
        int pp = ly + 8 * i;
        xo[(size_t)pp * CC + lx] = tile[lx][pp];
    }
}

// ---------------- kernel T2: weight re-layouts -------------------------------
__global__ void build_weights_kernel(const float* __restrict__ cw,
                                     const float* __restrict__ ow,
                                     float* __restrict__ wt,
                                     float* __restrict__ owt) {
    int idx = blockIdx.x * 256 + threadIdx.x;
    if (idx < OO * CC * K2) {            // conv_w (o,c,k) -> wt[k][c][o]
        int o = idx / (CC * K2);
        int r = idx % (CC * K2);
        int c = r / K2;
        int k = r % K2;
        wt[(k * CC + c) * OO + o] = cw[idx];
    }
    if (idx < NOFF * CC * K2) {          // offset_w (j,c,k) -> owt[c][k][j] (stride 20)
        int j = idx / (CC * K2);
        int r = idx % (CC * K2);
        int c = r / K2;
        int k = r % K2;
        owt[(c * K2 + k) * 20 + j] = ow[idx];
    }
}

// ---------------- kernel 1: offset conv (f32x2, j-pair packed) --------------
__global__ void __launch_bounds__(256) offset_conv_kernel(
    const float* __restrict__ x, const float* __restrict__ owt,
    const float* __restrict__ ob, float* __restrict__ offs)
{
    __shared__ float ws[CC * K2 * 20];    // 46080 B
    __shared__ float bs[NOFF];
    int tid = threadIdx.x;
    for (int i = tid; i < CC * K2 * 20; i += 256) ws[i] = owt[i];
    if (tid < NOFF) bs[tid] = ob[tid];
    __syncthreads();

    int flat = blockIdx.x * 256 + tid;     // 0 .. 36863
    int b = flat / HW, p = flat % HW;
    int h = p / WW, w = p % WW;
    const float* x0 = x + (size_t)b * CC * HW;
    const float* x1 = x0 + (size_t)4 * CC * HW;

    ull a0[9], a1[9];
#pragma unroll
    for (int j = 0; j < 9; j++) { a0[j] = 0ull; a1[j] = 0ull; }

    int yy[3], xx[3]; bool vy[3], vx[3];
#pragma unroll
    for (int d = 0; d < 3; d++) {
        yy[d] = h + d - 1; vy[d] = (unsigned)yy[d] < (unsigned)HH;
        xx[d] = w + d - 1; vx[d] = (unsigned)xx[d] < (unsigned)WW;
    }

    for (int c = 0; c < CC; c++) {
        float xv0[9], xv1[9];
        const float* xc0 = x0 + (size_t)c * HW;
        const float* xc1 = x1 + (size_t)c * HW;
#pragma unroll
        for (int dy = 0; dy < 3; dy++)
#pragma unroll
            for (int dx = 0; dx < 3; dx++) {
                int i = dy * 3 + dx;
                bool v = vy[dy] && vx[dx];
                int off = yy[dy] * WW + xx[dx];
                xv0[i] = v ? xc0[off] : 0.f;
                xv1[i] = v ? xc1[off] : 0.f;
            }
#pragma unroll
        for (int i = 0; i < 9; i++) {
            const float* row = ws + (c * K2 + i) * 20;
            ull s0, s1;
            PACKF2(s0, xv0[i], xv0[i]);
            PACKF2(s1, xv1[i], xv1[i]);
#pragma unroll
            for (int j = 0; j < 9; j++) {
                ull wv = *(const ull*)(row + 2 * j);
                FMA2(a0[j], s0, wv, a0[j]);
                FMA2(a1[j], s1, wv, a1[j]);
            }
        }
    }
    float* o0 = offs + (size_t)flat * NOFF;
    float* o1 = offs + (size_t)(flat + 36864) * NOFF;
#pragma unroll
    for (int j = 0; j < 9; j++) {
        float lo, hi;
        UNPKF2(lo, hi, a0[j]);
        *(float2*)(o0 + 2 * j) = make_float2(lo + bs[2 * j], hi + bs[2 * j + 1]);
        UNPKF2(lo, hi, a1[j]);
        *(float2*)(o1 + 2 * j) = make_float2(lo + bs[2 * j], hi + bs[2 * j + 1]);
    }
}

// ---------------- kernel 2: fused sampling + f32x2 GEMM ---------------------
// CTA: 128 threads, tile = 128 px x 64 out. Per thread: 8 px x 8 out.
// smem: samp double buffer [px][68] per tap + ws double buffer [c][64] per tap.
#define SAMP_ST 68
#define SAMP_SZ (128 * SAMP_ST)          // floats per buffer (8704)
#define WS_SZ   (CC * OO)                // 4096
#define SMEM_FUSED ((2 * SAMP_SZ + 2 * WS_SZ) * 4)   // 102400 B

__device__ __forceinline__ void fill_tap(
    const float* __restrict__ xt_b, const float* __restrict__ offs_b,
    int p0, int tap, float* __restrict__ sbuf, int warp, int lane)
{
    int kdy = tap / 3 - 1, kdx = tap % 3 - 1;
    int c = 2 * lane;
    for (int px = warp; px < 128; px += 4) {
        int p = p0 + px;
        int h = p / WW, w = p - h * WW;
        float2 od = *(const float2*)(offs_b + (size_t)p * NOFF + 2 * tap);
        float py  = (float)(h + kdy) + od.x;
        float pxf = (float)(w + kdx) + od.y;
        float fy = floorf(py), fx = floorf(pxf);
        int y0 = (int)fy, x0 = (int)fx;
        float wy = py - fy, wx = pxf - fx;
        bool vy0 = (unsigned)y0 < (unsigned)HH;
        bool vy1 = (unsigned)(y0 + 1) < (unsigned)HH;
        bool vx0 = (unsigned)x0 < (unsigned)WW;
        bool vx1 = (unsigned)(x0 + 1) < (unsigned)WW;
        const float* base = xt_b + ((ptrdiff_t)y0 * WW + x0) * CC + c;
        float2 z = make_float2(0.f, 0.f);
        float2 g00 = (vy0 && vx0) ? *(const float2*)(base)              : z;
        float2 g01 = (vy0 && vx1) ? *(const float2*)(base + CC)         : z;
        float2 g10 = (vy1 && vx0) ? *(const float2*)(base + WW*CC)      : z;
        float2 g11 = (vy1 && vx1) ? *(const float2*)(base + WW*CC + CC) : z;
        float w00 = (1.f - wy) * (1.f - wx);
        float w01 = (1.f - wy) * wx;
        float w10 = wy * (1.f - wx);
        float w11 = wy * wx;
        float sx = g00.x * w00 + g01.x * w01 + g10.x * w10 + g11.x * w11;
        float sy = g00.y * w00 + g01.y * w01 + g10.y * w10 + g11.y * w11;
        *(float2*)(sbuf + px * SAMP_ST + c) = make_float2(sx, sy);
    }
}

__global__ void __launch_bounds__(128) fused_deform_kernel(
    const float* __restrict__ xt, const float* __restrict__ offs,
    const float* __restrict__ wt, const float* __restrict__ cb,
    float* __restrict__ out)
{
    extern __shared__ float sm[];
    float* samp = sm;                    // 2 * 8704
    float* wsb  = sm + 2 * SAMP_SZ;      // 2 * 4096

    int tid  = threadIdx.x;
    int tx   = tid & 7;                  // out group (8 outs)
    int ty   = tid >> 3;                 // px group (8 px, strided 16)
    int warp = tid >> 5;
    int lane = tid & 31;
    int b    = blockIdx.x / 72;
    int p0   = (blockIdx.x % 72) * 128;

    const float* xt_b   = xt   + (size_t)b * HW * CC;
    const float* offs_b = offs + (size_t)b * HW * NOFF;

    ull acc[8][4];
#pragma unroll
    for (int i = 0; i < 8; i++)
#pragma unroll
        for (int j = 0; j < 4; j++) acc[i][j] = 0ull;

    // prologue: tap 0
    {
        const float4* src = (const float4*)(wt);
        float4* dst = (float4*)(wsb);
#pragma unroll
        for (int r = 0; r < 8; r++) dst[tid + 128 * r] = src[tid + 128 * r];
        fill_tap(xt_b, offs_b, p0, 0, samp, warp, lane);
    }

    int txo = tx * 8;
    for (int ck = 0; ck < 9; ck++) {
        __syncthreads();
        int cur = ck & 1, nxt = cur ^ 1;
        if (ck < 8) {
            const float4* src = (const float4*)(wt + (ck + 1) * WS_SZ);
            float4* dst = (float4*)(wsb + nxt * WS_SZ);
#pragma unroll
            for (int r = 0; r < 8; r++) dst[tid + 128 * r] = src[tid + 128 * r];
            fill_tap(xt_b, offs_b, p0, ck + 1, samp + nxt * SAMP_SZ, warp, lane);
        }

        const float* sb = samp + cur * SAMP_SZ;
        const float* wb = wsb  + cur * WS_SZ;
#pragma unroll 2
        for (int cc = 0; cc < 64; cc += 4) {
            float4 sv[8];
#pragma unroll
            for (int i = 0; i < 8; i++)
                sv[i] = *(const float4*)(sb + (ty + 16 * i) * SAMP_ST + cc);
#pragma unroll
            for (int r = 0; r < 4; r++) {
                float4 wa = *(const float4*)(wb + (cc + r) * 64 + txo);
                float4 wc = *(const float4*)(wb + (cc + r) * 64 + txo + 4);
                ull w0, w1, w2, w3;
                PACKF2(w0, wa.x, wa.y);
                PACKF2(w1, wa.z, wa.w);
                PACKF2(w2, wc.x, wc.y);
                PACKF2(w3, wc.z, wc.w);
#pragma unroll
                for (int i = 0; i < 8; i++) {
                    float s = (r == 0) ? sv[i].x : (r == 1) ? sv[i].y :
                              (r == 2) ? sv[i].z : sv[i].w;
                    ull ss;
                    PACKF2(ss, s, s);
                    FMA2(acc[i][0], ss, w0, acc[i][0]);
                    FMA2(acc[i][1], ss, w1, acc[i][1]);
                    FMA2(acc[i][2], ss, w2, acc[i][2]);
                    FMA2(acc[i][3], ss, w3, acc[i][3]);
                }
            }
        }
    }

    // epilogue: bias + scattered stores (px strided 16)
    float4 ba = *(const float4*)(cb + txo);
    float4 bc = *(const float4*)(cb + txo + 4);
    float bv[8] = {ba.x, ba.y, ba.z, ba.w, bc.x, bc.y, bc.z, bc.w};
    int obase = b * OO + txo;
#pragma unroll
    for (int j = 0; j < 4; j++) {
        float* oL = out + (size_t)(obase + 2 * j) * HW + p0 + ty;
        float* oH = oL + HW;
#pragma unroll
        for (int i = 0; i < 8; i++) {
            float lo, hi;
            UNPKF2(lo, hi, acc[i][j]);
            oL[16 * i] = lo + bv[2 * j];
            oH[16 * i] = hi + bv[2 * j + 1];
        }
    }
}

// ---------------- launch ------------------------------------------------------
extern "C" void kernel_launch(void* const* d_in, const int* in_sizes, int n_in,
                              void* d_out, int out_size) {
    const float* x  = (const float*)d_in[0];
    const float* ow = (const float*)d_in[1];
    const float* ob = (const float*)d_in[2];
    const float* cw = (const float*)d_in[3];
    const float* cb = (const float*)d_in[4];
    float* out = (float*)d_out;

    float *xt, *offs, *wt, *owt;
    cudaGetSymbolAddress((void**)&xt,   g_xt);
    cudaGetSymbolAddress((void**)&offs, g_offs);
    cudaGetSymbolAddress((void**)&wt,   g_wt);
    cudaGetSymbolAddress((void**)&owt,  g_owt);

    cudaFuncSetAttribute(fused_deform_kernel,
                         cudaFuncAttributeMaxDynamicSharedMemorySize, SMEM_FUSED);

    transpose_x_kernel<<<4608, 256>>>(x, xt);
    build_weights_kernel<<<144, 256>>>(cw, ow, wt, owt);
    offset_conv_kernel<<<144, 256>>>(x, owt, ob, offs);
    fused_deform_kernel<<<576, 128, SMEM_FUSED>>>(xt, offs, wt, cb, out);
}